// round 1
// baseline (speedup 1.0000x reference)
#include <cuda_runtime.h>
#include <cuda_bf16.h>
#include <cstdint>

#define BB 32
#define CC 64
#define NN 1024
#define DEPTH 8
#define NCLS 10

static __device__ float g_X[2][BB * NN * CC];   // ping-pong token states
static __device__ float g_Q[BB * NN * CC];
static __device__ float g_K[BB * NN * CC];
static __device__ float g_V[BB * NN * CC];

// ---------------------------------------------------------------------------
// Transpose: image (B,C,1024) -> X[0] (B,1024,C)
// ---------------------------------------------------------------------------
__global__ void k_transpose(const float* __restrict__ img) {
    __shared__ float t[64][65];
    int b = blockIdx.y;
    int n0 = blockIdx.x * 64;
    const float* src = img + (size_t)b * CC * NN;
    for (int idx = threadIdx.x; idx < 64 * 64; idx += 256) {
        int c = idx >> 6, n = idx & 63;
        t[c][n] = src[c * NN + n0 + n];
    }
    __syncthreads();
    float* dst = g_X[0] + ((size_t)b * NN + n0) * CC;
    for (int idx = threadIdx.x; idx < 64 * 64; idx += 256) {
        int n = idx >> 6, c = idx & 63;
        dst[n * CC + c] = t[c][n];
    }
}

// ---------------------------------------------------------------------------
// Fused QKV: Q = (X @ WQ) * scale, K = X @ WK, V = X @ WV
// Block: 64 rows x 192 cols, 256 threads, 4x12 register tile / thread.
// ---------------------------------------------------------------------------
__global__ void __launch_bounds__(256) k_qkv(const float* __restrict__ WQ,
                                             const float* __restrict__ WK,
                                             const float* __restrict__ WV,
                                             int pp) {
    extern __shared__ float sm[];
    float* Xs = sm;              // 64 x 65
    float* Ws = sm + 64 * 65;    // 64 x 192  (Q|K|V columns)
    const float SCALE = 0.03125f;  // 1/sqrt(1024)

    int b = blockIdx.y;
    int n0 = blockIdx.x * 64;
    int tid = threadIdx.x;

    const float* Xin = g_X[pp] + ((size_t)b * NN + n0) * CC;
    for (int idx = tid; idx < 64 * 64; idx += 256) {
        int r = idx >> 6, k = idx & 63;
        Xs[r * 65 + k] = Xin[idx];
    }
    for (int idx = tid; idx < 64 * 192; idx += 256) {
        int k = idx / 192, c = idx - k * 192;
        float v;
        if (c < 64)       v = WQ[k * 64 + c];
        else if (c < 128) v = WK[k * 64 + c - 64];
        else              v = WV[k * 64 + c - 128];
        Ws[idx] = v;
    }
    __syncthreads();

    int tx = tid & 15, ty = tid >> 4;
    float acc[4][12];
#pragma unroll
    for (int i = 0; i < 4; i++)
#pragma unroll
        for (int j = 0; j < 12; j++) acc[i][j] = 0.0f;

#pragma unroll 8
    for (int k = 0; k < 64; ++k) {
        float xv[4];
#pragma unroll
        for (int i = 0; i < 4; i++) xv[i] = Xs[(ty * 4 + i) * 65 + k];
        float wv[12];
#pragma unroll
        for (int j = 0; j < 12; j++) wv[j] = Ws[k * 192 + tx + 16 * j];
#pragma unroll
        for (int i = 0; i < 4; i++)
#pragma unroll
            for (int j = 0; j < 12; j++) acc[i][j] += xv[i] * wv[j];
    }

    size_t base = ((size_t)b * NN + n0) * CC;
    float* Qo = g_Q + base;
    float* Ko = g_K + base;
    float* Vo = g_V + base;
#pragma unroll
    for (int i = 0; i < 4; i++) {
        int r = ty * 4 + i;
#pragma unroll
        for (int j = 0; j < 4; j++) {
            Qo[r * 64 + tx + 16 * j] = acc[i][j] * SCALE;
            Ko[r * 64 + tx + 16 * j] = acc[i][4 + j];
            Vo[r * 64 + tx + 16 * j] = acc[i][8 + j];
        }
    }
}

// ---------------------------------------------------------------------------
// Flash attention + residual: Xout = softmax(Q Kt) @ V + Xin
// CTA = (64-row tile, batch). 256 threads (16x16). Online softmax, running
// (m,l) replicated per-thread across tx (deterministic after shuffles).
// ---------------------------------------------------------------------------
#define QKSTRIDE 68   // pad for conflict-free float4 row reads

__global__ void __launch_bounds__(256) k_attn(int pp) {
    extern __shared__ float sm[];
    float* Qs = sm;                        // 64 x 68
    float* Ks = Qs + 64 * QKSTRIDE;        // 64 x 68
    float* Vs = Ks + 64 * QKSTRIDE;        // 64 x 64
    float* Ps = Vs + 64 * 64;              // 64 x 65

    int b = blockIdx.y;
    int n0 = blockIdx.x * 64;
    int tid = threadIdx.x, tx = tid & 15, ty = tid >> 4;

    const float* Qg = g_Q + ((size_t)b * NN + n0) * CC;
    const float* Kg = g_K + (size_t)b * NN * CC;
    const float* Vg = g_V + (size_t)b * NN * CC;

    for (int idx = tid; idx < 4096; idx += 256) {
        int r = idx >> 6, c = idx & 63;
        Qs[r * QKSTRIDE + c] = Qg[idx];
    }

    float o[4][4];
    float mrun[4], lrun[4];
#pragma unroll
    for (int i = 0; i < 4; i++) {
        mrun[i] = -1e30f;
        lrun[i] = 0.0f;
#pragma unroll
        for (int j = 0; j < 4; j++) o[i][j] = 0.0f;
    }

    for (int kt = 0; kt < 16; ++kt) {
        __syncthreads();   // previous P@V done before Ks/Vs/Ps reuse
        const float* Kt = Kg + kt * 64 * 64;
        const float* Vt = Vg + kt * 64 * 64;
        for (int idx = tid; idx < 4096; idx += 256) {
            int r = idx >> 6, c = idx & 63;
            Ks[r * QKSTRIDE + c] = Kt[idx];
            Vs[idx] = Vt[idx];
        }
        __syncthreads();

        // S = Qs @ Ks^T   (rows ty*4+i, key-cols tx+16*j)
        float s[4][4];
#pragma unroll
        for (int i = 0; i < 4; i++)
#pragma unroll
            for (int j = 0; j < 4; j++) s[i][j] = 0.0f;

#pragma unroll 4
        for (int c = 0; c < 64; c += 4) {
            float4 q[4], kk[4];
#pragma unroll
            for (int i = 0; i < 4; i++)
                q[i] = *(const float4*)&Qs[(ty * 4 + i) * QKSTRIDE + c];
#pragma unroll
            for (int j = 0; j < 4; j++)
                kk[j] = *(const float4*)&Ks[(tx + 16 * j) * QKSTRIDE + c];
#pragma unroll
            for (int i = 0; i < 4; i++)
#pragma unroll
                for (int j = 0; j < 4; j++) {
                    s[i][j] += q[i].x * kk[j].x;
                    s[i][j] += q[i].y * kk[j].y;
                    s[i][j] += q[i].z * kk[j].z;
                    s[i][j] += q[i].w * kk[j].w;
                }
        }

        // online softmax update; P -> smem
#pragma unroll
        for (int i = 0; i < 4; i++) {
            float mx = fmaxf(fmaxf(s[i][0], s[i][1]), fmaxf(s[i][2], s[i][3]));
#pragma unroll
            for (int d = 1; d < 16; d <<= 1)
                mx = fmaxf(mx, __shfl_xor_sync(0xffffffffu, mx, d, 16));
            float mnew = fmaxf(mrun[i], mx);
            float corr = __expf(mrun[i] - mnew);
            float rs = 0.0f;
#pragma unroll
            for (int j = 0; j < 4; j++) {
                float p = __expf(s[i][j] - mnew);
                s[i][j] = p;
                rs += p;
            }
#pragma unroll
            for (int d = 1; d < 16; d <<= 1)
                rs += __shfl_xor_sync(0xffffffffu, rs, d, 16);
            lrun[i] = lrun[i] * corr + rs;
            mrun[i] = mnew;
#pragma unroll
            for (int j = 0; j < 4; j++) o[i][j] *= corr;
#pragma unroll
            for (int j = 0; j < 4; j++)
                Ps[(ty * 4 + i) * 65 + tx + 16 * j] = s[i][j];
        }
        __syncthreads();

        // O += P @ V   (output cols tx*4+j for float4 V reads)
#pragma unroll 8
        for (int k = 0; k < 64; ++k) {
            float4 vv = *(const float4*)&Vs[k * 64 + tx * 4];
            float pv[4];
#pragma unroll
            for (int i = 0; i < 4; i++) pv[i] = Ps[(ty * 4 + i) * 65 + k];
#pragma unroll
            for (int i = 0; i < 4; i++) {
                o[i][0] += pv[i] * vv.x;
                o[i][1] += pv[i] * vv.y;
                o[i][2] += pv[i] * vv.z;
                o[i][3] += pv[i] * vv.w;
            }
        }
    }

    // epilogue: Xout = O / l + Xin
    const float* Xin = g_X[pp] + ((size_t)b * NN + n0) * CC;
    float* Xout = g_X[pp ^ 1] + ((size_t)b * NN + n0) * CC;
#pragma unroll
    for (int i = 0; i < 4; i++) {
        float inv = 1.0f / lrun[i];
        int r = ty * 4 + i;
        float4 xi = *(const float4*)&Xin[r * 64 + tx * 4];
        float4 res;
        res.x = o[i][0] * inv + xi.x;
        res.y = o[i][1] * inv + xi.y;
        res.z = o[i][2] * inv + xi.z;
        res.w = o[i][3] * inv + xi.w;
        *(float4*)&Xout[r * 64 + tx * 4] = res;
    }
}

// ---------------------------------------------------------------------------
// Head: pred[b] = mean_c(X[b]) @ last_W^T + last_b
// ---------------------------------------------------------------------------
__global__ void k_head(const float* __restrict__ lw,
                       const float* __restrict__ lb,
                       float* __restrict__ out) {
    __shared__ float meanv[NN];
    __shared__ float red[8];
    int b = blockIdx.x;
    const float* Xb = g_X[0] + (size_t)b * NN * CC;   // DEPTH even -> final in buf 0

    for (int n = threadIdx.x; n < NN; n += 256) {
        const float4* p = (const float4*)(Xb + (size_t)n * CC);
        float s = 0.0f;
#pragma unroll
        for (int q = 0; q < 16; q++) {
            float4 v = p[q];
            s += v.x + v.y + v.z + v.w;
        }
        meanv[n] = s * (1.0f / 64.0f);
    }
    __syncthreads();

    for (int cls = 0; cls < NCLS; cls++) {
        float s = 0.0f;
        for (int n = threadIdx.x; n < NN; n += 256)
            s += meanv[n] * lw[cls * NN + n];
#pragma unroll
        for (int d = 16; d; d >>= 1) s += __shfl_xor_sync(0xffffffffu, s, d);
        if ((threadIdx.x & 31) == 0) red[threadIdx.x >> 5] = s;
        __syncthreads();
        if (threadIdx.x == 0) {
            float t = 0.0f;
#pragma unroll
            for (int w = 0; w < 8; w++) t += red[w];
            out[b * NCLS + cls] = t + lb[cls];
        }
        __syncthreads();
    }
}

// ---------------------------------------------------------------------------
extern "C" void kernel_launch(void* const* d_in, const int* in_sizes, int n_in,
                              void* d_out, int out_size) {
    (void)in_sizes; (void)n_in; (void)out_size;
    const float* img = (const float*)d_in[0];
    const float* WV  = (const float*)d_in[1];
    const float* WK  = (const float*)d_in[2];
    const float* WQ  = (const float*)d_in[3];
    const float* lw  = (const float*)d_in[4];
    const float* lb  = (const float*)d_in[5];
    float* out = (float*)d_out;

    const int QKV_SMEM  = (64 * 65 + 64 * 192) * 4;                         // 65792
    const int ATTN_SMEM = (64 * QKSTRIDE * 2 + 64 * 64 + 64 * 65) * 4;      // 67840
    cudaFuncSetAttribute(k_qkv,  cudaFuncAttributeMaxDynamicSharedMemorySize, QKV_SMEM);
    cudaFuncSetAttribute(k_attn, cudaFuncAttributeMaxDynamicSharedMemorySize, ATTN_SMEM);

    dim3 grid(16, 32), blk(256);
    k_transpose<<<grid, blk>>>(img);
    for (int l = 0; l < DEPTH; l++) {
        k_qkv<<<grid, blk, QKV_SMEM>>>(WQ, WK, WV, l & 1);
        k_attn<<<grid, blk, ATTN_SMEM>>>(l & 1);
    }
    k_head<<<32, blk>>>(lw, lb, out);
}

// round 2
// speedup vs baseline: 1.0741x; 1.0741x over previous
#include <cuda_runtime.h>
#include <cuda_bf16.h>
#include <cstdint>

#define BB 32
#define CC 64
#define NN 1024
#define DEPTH 8
#define NCLS 10

using u64 = unsigned long long;

static __device__ float g_X[2][BB * NN * CC];   // ping-pong token states
static __device__ float g_Q[BB * NN * CC];
static __device__ float g_K[BB * NN * CC];
static __device__ float g_V[BB * NN * CC];

// ---------------- packed fp32 helpers (Blackwell f32x2 pipe) ----------------
__device__ __forceinline__ u64 ffma2(u64 a, u64 b, u64 c) {
    u64 d;
    asm("fma.rn.f32x2 %0, %1, %2, %3;" : "=l"(d) : "l"(a), "l"(b), "l"(c));
    return d;
}
__device__ __forceinline__ u64 fmul2(u64 a, u64 b) {
    u64 d;
    asm("mul.rn.f32x2 %0, %1, %2;" : "=l"(d) : "l"(a), "l"(b));
    return d;
}
__device__ __forceinline__ u64 dup2(float x) {
    u64 r;
    asm("mov.b64 %0, {%1, %1};" : "=l"(r) : "f"(x));
    return r;
}
__device__ __forceinline__ float2 u2f2(u64 v) {
    float2 r;
    asm("mov.b64 {%0, %1}, %2;" : "=f"(r.x), "=f"(r.y) : "l"(v));
    return r;
}

// ---------------------------------------------------------------------------
// Transpose: image (B,C,1024) -> X[0] (B,1024,C)
// ---------------------------------------------------------------------------
__global__ void k_transpose(const float* __restrict__ img) {
    __shared__ float t[64][65];
    int b = blockIdx.y;
    int n0 = blockIdx.x * 64;
    const float* src = img + (size_t)b * CC * NN;
    for (int idx = threadIdx.x; idx < 64 * 64; idx += 256) {
        int c = idx >> 6, n = idx & 63;
        t[c][n] = src[c * NN + n0 + n];
    }
    __syncthreads();
    float* dst = g_X[0] + ((size_t)b * NN + n0) * CC;
    for (int idx = threadIdx.x; idx < 64 * 64; idx += 256) {
        int n = idx >> 6, c = idx & 63;
        dst[n * CC + c] = t[c][n];
    }
}

// ---------------------------------------------------------------------------
// Fused QKV (f32x2): Q = (X @ WQ) * scale, K = X @ WK, V = X @ WV
// Block: 64 rows x 192 cols, 256 threads, per-thread 4 rows x 6 col-pairs.
// ---------------------------------------------------------------------------
#define XSTRIDE 68

__global__ void __launch_bounds__(256) k_qkv(const float* __restrict__ WQ,
                                             const float* __restrict__ WK,
                                             const float* __restrict__ WV,
                                             int pp) {
    extern __shared__ float sm[];
    float* Xs = sm;                   // 64 x 68
    float* Ws = sm + 64 * XSTRIDE;    // 64 x 192  (Q|K|V columns)

    int b = blockIdx.y;
    int n0 = blockIdx.x * 64;
    int tid = threadIdx.x;

    const float* Xin = g_X[pp] + ((size_t)b * NN + n0) * CC;
    for (int idx = tid; idx < 1024; idx += 256) {
        int r = idx >> 4, c = (idx & 15) << 2;
        *(float4*)&Xs[r * XSTRIDE + c] = *(const float4*)&Xin[r * 64 + c];
    }
    for (int idx = tid; idx < 64 * 192; idx += 256) {
        int k = idx / 192, c = idx - k * 192;
        float v;
        if (c < 64)       v = WQ[k * 64 + c];
        else if (c < 128) v = WK[k * 64 + c - 64];
        else              v = WV[k * 64 + c - 128];
        Ws[idx] = v;
    }
    __syncthreads();

    int tx = tid & 15, ty = tid >> 4;
    u64 acc[4][6];
#pragma unroll
    for (int i = 0; i < 4; i++)
#pragma unroll
        for (int j = 0; j < 6; j++) acc[i][j] = 0ULL;

#pragma unroll 2
    for (int k0 = 0; k0 < 64; k0 += 4) {
        float4 xv[4];
#pragma unroll
        for (int i = 0; i < 4; i++)
            xv[i] = *(const float4*)&Xs[(ty * 4 + i) * XSTRIDE + k0];
#pragma unroll
        for (int kk = 0; kk < 4; kk++) {
            u64 wv[6];
#pragma unroll
            for (int j = 0; j < 6; j++)
                wv[j] = *(const u64*)&Ws[(k0 + kk) * 192 + tx * 2 + 32 * j];
            u64 xd[4];
            xd[0] = dup2(kk == 0 ? xv[0].x : kk == 1 ? xv[0].y : kk == 2 ? xv[0].z : xv[0].w);
            xd[1] = dup2(kk == 0 ? xv[1].x : kk == 1 ? xv[1].y : kk == 2 ? xv[1].z : xv[1].w);
            xd[2] = dup2(kk == 0 ? xv[2].x : kk == 1 ? xv[2].y : kk == 2 ? xv[2].z : xv[2].w);
            xd[3] = dup2(kk == 0 ? xv[3].x : kk == 1 ? xv[3].y : kk == 2 ? xv[3].z : xv[3].w);
#pragma unroll
            for (int i = 0; i < 4; i++)
#pragma unroll
                for (int j = 0; j < 6; j++)
                    acc[i][j] = ffma2(xd[i], wv[j], acc[i][j]);
        }
    }

    const u64 scale2 = dup2(0.03125f);   // 1/sqrt(1024)
    size_t base = ((size_t)b * NN + n0) * CC;
    float* Qo = g_Q + base;
    float* Ko = g_K + base;
    float* Vo = g_V + base;
#pragma unroll
    for (int i = 0; i < 4; i++) {
        int r = ty * 4 + i;
        int co = tx * 2;
#pragma unroll
        for (int j = 0; j < 2; j++) {
            *(u64*)&Qo[r * 64 + co + 32 * j] = fmul2(acc[i][j], scale2);
            *(u64*)&Ko[r * 64 + co + 32 * j] = acc[i][2 + j];
            *(u64*)&Vo[r * 64 + co + 32 * j] = acc[i][4 + j];
        }
    }
}

// ---------------------------------------------------------------------------
// Flash attention + residual (f32x2): Xout = softmax(Q Kt) @ V + Xin
// CTA = (64-row tile, batch). 256 threads (16x16). Online softmax.
// ---------------------------------------------------------------------------
#define QKSTRIDE 68

__global__ void __launch_bounds__(256) k_attn(int pp) {
    extern __shared__ float sm[];
    float* Qs = sm;                        // 64 x 68
    float* Ks = Qs + 64 * QKSTRIDE;        // 64 x 68
    float* Ps = Ks + 64 * QKSTRIDE;        // 64 x 68
    float* Vs = Ps + 64 * QKSTRIDE;        // 64 x 64

    int b = blockIdx.y;
    int n0 = blockIdx.x * 64;
    int tid = threadIdx.x, tx = tid & 15, ty = tid >> 4;

    const float* Qg = g_Q + ((size_t)b * NN + n0) * CC;
    const float* Kg = g_K + (size_t)b * NN * CC;
    const float* Vg = g_V + (size_t)b * NN * CC;

    for (int idx = tid; idx < 1024; idx += 256) {
        int r = idx >> 4, c = (idx & 15) << 2;
        *(float4*)&Qs[r * QKSTRIDE + c] = *(const float4*)&Qg[r * 64 + c];
    }

    u64 o2[4][2];
    float mrun[4], lrun[4];
#pragma unroll
    for (int i = 0; i < 4; i++) {
        mrun[i] = -1e30f;
        lrun[i] = 0.0f;
        o2[i][0] = 0ULL;
        o2[i][1] = 0ULL;
    }

#pragma unroll 1
    for (int kt = 0; kt < 16; ++kt) {
        __syncthreads();   // previous P@V done before Ks/Vs/Ps reuse
        const float* Kt = Kg + kt * 64 * 64;
        const float* Vt = Vg + kt * 64 * 64;
        for (int idx = tid; idx < 1024; idx += 256) {
            int r = idx >> 4, c = (idx & 15) << 2;
            *(float4*)&Ks[r * QKSTRIDE + c] = *(const float4*)&Kt[r * 64 + c];
            *(float4*)&Vs[r * 64 + c]       = *(const float4*)&Vt[r * 64 + c];
        }
        __syncthreads();

        // S = Qs @ Ks^T, reduction packed over channel pairs
        u64 acc[4][4];
#pragma unroll
        for (int i = 0; i < 4; i++)
#pragma unroll
            for (int j = 0; j < 4; j++) acc[i][j] = 0ULL;

#pragma unroll 4
        for (int c = 0; c < 64; c += 4) {
            ulonglong2 q[4], kk[4];
#pragma unroll
            for (int i = 0; i < 4; i++)
                q[i] = *(const ulonglong2*)&Qs[(ty * 4 + i) * QKSTRIDE + c];
#pragma unroll
            for (int j = 0; j < 4; j++)
                kk[j] = *(const ulonglong2*)&Ks[(tx + 16 * j) * QKSTRIDE + c];
#pragma unroll
            for (int i = 0; i < 4; i++)
#pragma unroll
                for (int j = 0; j < 4; j++) {
                    acc[i][j] = ffma2(q[i].x, kk[j].x, acc[i][j]);
                    acc[i][j] = ffma2(q[i].y, kk[j].y, acc[i][j]);
                }
        }

        float s[4][4];
#pragma unroll
        for (int i = 0; i < 4; i++)
#pragma unroll
            for (int j = 0; j < 4; j++) {
                float2 p = u2f2(acc[i][j]);
                s[i][j] = p.x + p.y;
            }

        // online softmax update; P -> smem
#pragma unroll
        for (int i = 0; i < 4; i++) {
            float mx = fmaxf(fmaxf(s[i][0], s[i][1]), fmaxf(s[i][2], s[i][3]));
#pragma unroll
            for (int d = 1; d < 16; d <<= 1)
                mx = fmaxf(mx, __shfl_xor_sync(0xffffffffu, mx, d, 16));
            float mnew = fmaxf(mrun[i], mx);
            float corr = __expf(mrun[i] - mnew);
            float rs = 0.0f;
#pragma unroll
            for (int j = 0; j < 4; j++) {
                float p = __expf(s[i][j] - mnew);
                s[i][j] = p;
                rs += p;
            }
#pragma unroll
            for (int d = 1; d < 16; d <<= 1)
                rs += __shfl_xor_sync(0xffffffffu, rs, d, 16);
            lrun[i] = lrun[i] * corr + rs;
            mrun[i] = mnew;
            u64 c2 = dup2(corr);
            o2[i][0] = fmul2(o2[i][0], c2);
            o2[i][1] = fmul2(o2[i][1], c2);
#pragma unroll
            for (int j = 0; j < 4; j++)
                Ps[(ty * 4 + i) * QKSTRIDE + tx + 16 * j] = s[i][j];
        }
        __syncthreads();

        // O += P @ V   (output cols tx*4 + 0..3 as two packed pairs)
#pragma unroll 4
        for (int k0 = 0; k0 < 64; k0 += 4) {
            u64 va[4][2];
#pragma unroll
            for (int kk = 0; kk < 4; kk++) {
                ulonglong2 t = *(const ulonglong2*)&Vs[(k0 + kk) * 64 + tx * 4];
                va[kk][0] = t.x;
                va[kk][1] = t.y;
            }
#pragma unroll
            for (int i = 0; i < 4; i++) {
                float4 p = *(const float4*)&Ps[(ty * 4 + i) * QKSTRIDE + k0];
                u64 d0 = dup2(p.x), d1 = dup2(p.y), d2 = dup2(p.z), d3 = dup2(p.w);
                o2[i][0] = ffma2(d0, va[0][0], o2[i][0]);
                o2[i][1] = ffma2(d0, va[0][1], o2[i][1]);
                o2[i][0] = ffma2(d1, va[1][0], o2[i][0]);
                o2[i][1] = ffma2(d1, va[1][1], o2[i][1]);
                o2[i][0] = ffma2(d2, va[2][0], o2[i][0]);
                o2[i][1] = ffma2(d2, va[2][1], o2[i][1]);
                o2[i][0] = ffma2(d3, va[3][0], o2[i][0]);
                o2[i][1] = ffma2(d3, va[3][1], o2[i][1]);
            }
        }
    }

    // epilogue: Xout = O / l + Xin
    const float* Xin = g_X[pp] + ((size_t)b * NN + n0) * CC;
    float* Xout = g_X[pp ^ 1] + ((size_t)b * NN + n0) * CC;
#pragma unroll
    for (int i = 0; i < 4; i++) {
        float inv = 1.0f / lrun[i];
        int r = ty * 4 + i;
        float2 a = u2f2(o2[i][0]);
        float2 bb2 = u2f2(o2[i][1]);
        float4 xi = *(const float4*)&Xin[r * 64 + tx * 4];
        float4 res;
        res.x = a.x * inv + xi.x;
        res.y = a.y * inv + xi.y;
        res.z = bb2.x * inv + xi.z;
        res.w = bb2.y * inv + xi.w;
        *(float4*)&Xout[r * 64 + tx * 4] = res;
    }
}

// ---------------------------------------------------------------------------
// Head: pred[b] = mean_c(X[b]) @ last_W^T + last_b
// ---------------------------------------------------------------------------
__global__ void k_head(const float* __restrict__ lw,
                       const float* __restrict__ lb,
                       float* __restrict__ out) {
    __shared__ float meanv[NN];
    __shared__ float red[8];
    int b = blockIdx.x;
    const float* Xb = g_X[0] + (size_t)b * NN * CC;   // DEPTH even -> final in buf 0

    for (int n = threadIdx.x; n < NN; n += 256) {
        const float4* p = (const float4*)(Xb + (size_t)n * CC);
        float s = 0.0f;
#pragma unroll
        for (int q = 0; q < 16; q++) {
            float4 v = p[q];
            s += v.x + v.y + v.z + v.w;
        }
        meanv[n] = s * (1.0f / 64.0f);
    }
    __syncthreads();

    for (int cls = 0; cls < NCLS; cls++) {
        float s = 0.0f;
        for (int n = threadIdx.x; n < NN; n += 256)
            s += meanv[n] * lw[cls * NN + n];
#pragma unroll
        for (int d = 16; d; d >>= 1) s += __shfl_xor_sync(0xffffffffu, s, d);
        if ((threadIdx.x & 31) == 0) red[threadIdx.x >> 5] = s;
        __syncthreads();
        if (threadIdx.x == 0) {
            float t = 0.0f;
#pragma unroll
            for (int w = 0; w < 8; w++) t += red[w];
            out[b * NCLS + cls] = t + lb[cls];
        }
        __syncthreads();
    }
}

// ---------------------------------------------------------------------------
extern "C" void kernel_launch(void* const* d_in, const int* in_sizes, int n_in,
                              void* d_out, int out_size) {
    (void)in_sizes; (void)n_in; (void)out_size;
    const float* img = (const float*)d_in[0];
    const float* WV  = (const float*)d_in[1];
    const float* WK  = (const float*)d_in[2];
    const float* WQ  = (const float*)d_in[3];
    const float* lw  = (const float*)d_in[4];
    const float* lb  = (const float*)d_in[5];
    float* out = (float*)d_out;

    const int QKV_SMEM  = (64 * XSTRIDE + 64 * 192) * 4;                 // ~66.6 KB
    const int ATTN_SMEM = (64 * QKSTRIDE * 3 + 64 * 64) * 4;             // ~68.6 KB
    cudaFuncSetAttribute(k_qkv,  cudaFuncAttributeMaxDynamicSharedMemorySize, QKV_SMEM);
    cudaFuncSetAttribute(k_attn, cudaFuncAttributeMaxDynamicSharedMemorySize, ATTN_SMEM);

    dim3 grid(16, 32), blk(256);
    k_transpose<<<grid, blk>>>(img);
    for (int l = 0; l < DEPTH; l++) {
        k_qkv<<<grid, blk, QKV_SMEM>>>(WQ, WK, WV, l & 1);
        k_attn<<<grid, blk, ATTN_SMEM>>>(l & 1);
    }
    k_head<<<32, blk>>>(lw, lb, out);
}

// round 3
// speedup vs baseline: 1.2671x; 1.1797x over previous
#include <cuda_runtime.h>
#include <cuda_bf16.h>
#include <cstdint>

#define BB 32
#define CC 64
#define NN 1024
#define DEPTH 8
#define NCLS 10

using u64 = unsigned long long;

static __device__ float g_X[2][BB * NN * CC];   // ping-pong token states
static __device__ float g_Q[BB * NN * CC];
static __device__ float g_K[BB * NN * CC];
static __device__ float g_V[BB * NN * CC];

// ---------------- packed fp32 helpers (Blackwell f32x2 pipe) ----------------
__device__ __forceinline__ u64 ffma2(u64 a, u64 b, u64 c) {
    u64 d;
    asm("fma.rn.f32x2 %0, %1, %2, %3;" : "=l"(d) : "l"(a), "l"(b), "l"(c));
    return d;
}
__device__ __forceinline__ u64 fmul2(u64 a, u64 b) {
    u64 d;
    asm("mul.rn.f32x2 %0, %1, %2;" : "=l"(d) : "l"(a), "l"(b));
    return d;
}
__device__ __forceinline__ u64 dup2(float x) {
    u64 r;
    asm("mov.b64 %0, {%1, %1};" : "=l"(r) : "f"(x));
    return r;
}
__device__ __forceinline__ float2 u2f2(u64 v) {
    float2 r;
    asm("mov.b64 {%0, %1}, %2;" : "=f"(r.x), "=f"(r.y) : "l"(v));
    return r;
}

// ---------------- cp.async helpers ----------------
__device__ __forceinline__ void cp16(uint32_t dst, const float* src) {
    asm volatile("cp.async.cg.shared.global [%0], [%1], 16;" :: "r"(dst), "l"(src));
}
__device__ __forceinline__ void cp_commit() {
    asm volatile("cp.async.commit_group;" ::: "memory");
}
__device__ __forceinline__ void cp_wait0() {
    asm volatile("cp.async.wait_group 0;" ::: "memory");
}

// ---------------------------------------------------------------------------
// Transpose: image (B,C,1024) -> X[0] (B,1024,C)
// ---------------------------------------------------------------------------
__global__ void k_transpose(const float* __restrict__ img) {
    __shared__ float t[64][65];
    int b = blockIdx.y;
    int n0 = blockIdx.x * 64;
    const float* src = img + (size_t)b * CC * NN;
    for (int idx = threadIdx.x; idx < 64 * 64; idx += 256) {
        int c = idx >> 6, n = idx & 63;
        t[c][n] = src[c * NN + n0 + n];
    }
    __syncthreads();
    float* dst = g_X[0] + ((size_t)b * NN + n0) * CC;
    for (int idx = threadIdx.x; idx < 64 * 64; idx += 256) {
        int n = idx >> 6, c = idx & 63;
        dst[n * CC + c] = t[c][n];
    }
}

// ---------------------------------------------------------------------------
// Fused QKV (f32x2): Q = (X @ WQ) * scale, K = X @ WK, V = X @ WV
// Block: 64 rows x 192 cols, 256 threads, per-thread 4 rows x 6 col-pairs.
// X/W staged via cp.async.
// ---------------------------------------------------------------------------
#define XSTRIDE 68

__global__ void __launch_bounds__(256) k_qkv(const float* __restrict__ WQ,
                                             const float* __restrict__ WK,
                                             const float* __restrict__ WV,
                                             int pp) {
    extern __shared__ float sm[];
    float* Xs = sm;                   // 64 x 68
    float* Ws = sm + 64 * XSTRIDE;    // 64 x 192  (Q|K|V columns)
    uint32_t sXs = (uint32_t)__cvta_generic_to_shared(Xs);
    uint32_t sWs = (uint32_t)__cvta_generic_to_shared(Ws);

    int b = blockIdx.y;
    int n0 = blockIdx.x * 64;
    int tid = threadIdx.x;

    const float* Xin = g_X[pp] + ((size_t)b * NN + n0) * CC;
#pragma unroll
    for (int t = 0; t < 4; t++) {
        int i = tid + t * 256;
        int r = i >> 4, c = (i & 15) << 2;
        cp16(sXs + (r * XSTRIDE + c) * 4, Xin + r * 64 + c);
        cp16(sWs + (r * 192 + c) * 4,       WQ + r * 64 + c);
        cp16(sWs + (r * 192 + 64 + c) * 4,  WK + r * 64 + c);
        cp16(sWs + (r * 192 + 128 + c) * 4, WV + r * 64 + c);
    }
    cp_commit();

    int tx = tid & 15, ty = tid >> 4;
    u64 acc[4][6];
#pragma unroll
    for (int i = 0; i < 4; i++)
#pragma unroll
        for (int j = 0; j < 6; j++) acc[i][j] = 0ULL;

    cp_wait0();
    __syncthreads();

#pragma unroll 2
    for (int k0 = 0; k0 < 64; k0 += 4) {
        float4 xv[4];
#pragma unroll
        for (int i = 0; i < 4; i++)
            xv[i] = *(const float4*)&Xs[(ty * 4 + i) * XSTRIDE + k0];
#pragma unroll
        for (int kk = 0; kk < 4; kk++) {
            u64 wv[6];
#pragma unroll
            for (int j = 0; j < 6; j++)
                wv[j] = *(const u64*)&Ws[(k0 + kk) * 192 + tx * 2 + 32 * j];
            u64 xd[4];
            xd[0] = dup2(kk == 0 ? xv[0].x : kk == 1 ? xv[0].y : kk == 2 ? xv[0].z : xv[0].w);
            xd[1] = dup2(kk == 0 ? xv[1].x : kk == 1 ? xv[1].y : kk == 2 ? xv[1].z : xv[1].w);
            xd[2] = dup2(kk == 0 ? xv[2].x : kk == 1 ? xv[2].y : kk == 2 ? xv[2].z : xv[2].w);
            xd[3] = dup2(kk == 0 ? xv[3].x : kk == 1 ? xv[3].y : kk == 2 ? xv[3].z : xv[3].w);
#pragma unroll
            for (int i = 0; i < 4; i++)
#pragma unroll
                for (int j = 0; j < 6; j++)
                    acc[i][j] = ffma2(xd[i], wv[j], acc[i][j]);
        }
    }

    const u64 scale2 = dup2(0.03125f);   // 1/sqrt(1024)
    size_t base = ((size_t)b * NN + n0) * CC;
    float* Qo = g_Q + base;
    float* Ko = g_K + base;
    float* Vo = g_V + base;
#pragma unroll
    for (int i = 0; i < 4; i++) {
        int r = ty * 4 + i;
        int co = tx * 2;
#pragma unroll
        for (int j = 0; j < 2; j++) {
            *(u64*)&Qo[r * 64 + co + 32 * j] = fmul2(acc[i][j], scale2);
            *(u64*)&Ko[r * 64 + co + 32 * j] = acc[i][2 + j];
            *(u64*)&Vo[r * 64 + co + 32 * j] = acc[i][4 + j];
        }
    }
}

// ---------------------------------------------------------------------------
// Flash attention + residual: Xout = softmax(Q Kt) @ V + Xin
// cp.async double-buffered K/V. CTA = (64-row tile, batch). 256 threads.
// ---------------------------------------------------------------------------
#define QKSTRIDE 68

__global__ void __launch_bounds__(256) k_attn(int pp) {
    extern __shared__ float sm[];
    float* Qs = sm;                          // 64 x 68
    float* Ks0 = Qs + 64 * QKSTRIDE;         // 2 x (64 x 68)
    float* Vs0 = Ks0 + 2 * 64 * QKSTRIDE;    // 2 x (64 x 64)
    float* Ps = Vs0 + 2 * 64 * 64;           // 64 x 68
    uint32_t sQ = (uint32_t)__cvta_generic_to_shared(Qs);
    uint32_t sK = (uint32_t)__cvta_generic_to_shared(Ks0);
    uint32_t sV = (uint32_t)__cvta_generic_to_shared(Vs0);

    int b = blockIdx.y;
    int n0 = blockIdx.x * 64;
    int tid = threadIdx.x, tx = tid & 15, ty = tid >> 4;

    const float* Qg = g_Q + ((size_t)b * NN + n0) * CC;
    const float* Kg = g_K + (size_t)b * NN * CC;
    const float* Vg = g_V + (size_t)b * NN * CC;

    // prefetch Q + tile 0 (group 0)
#pragma unroll
    for (int t = 0; t < 4; t++) {
        int i = tid + t * 256;
        int r = i >> 4, c = (i & 15) << 2;
        cp16(sQ + (r * QKSTRIDE + c) * 4, Qg + r * 64 + c);
        cp16(sK + (r * QKSTRIDE + c) * 4, Kg + r * 64 + c);
        cp16(sV + (r * 64 + c) * 4,       Vg + r * 64 + c);
    }
    cp_commit();

    u64 o2[4][2];
    float mrun[4], lrun[4];
#pragma unroll
    for (int i = 0; i < 4; i++) {
        mrun[i] = -1e30f;
        lrun[i] = 0.0f;
        o2[i][0] = 0ULL;
        o2[i][1] = 0ULL;
    }

#pragma unroll 1
    for (int kt = 0; kt < 16; ++kt) {
        int buf = kt & 1;
        const float* Ks = Ks0 + buf * 64 * QKSTRIDE;
        const float* Vs = Vs0 + buf * 64 * 64;

        cp_wait0();        // tile kt resident (this thread's copies done)
        __syncthreads();   // all threads' copies visible; prev PV done

        // issue prefetch of tile kt+1 into the other buffer
        if (kt + 1 < 16) {
            int nb = (kt + 1) & 1;
            const float* Kt = Kg + (kt + 1) * 64 * 64;
            const float* Vt = Vg + (kt + 1) * 64 * 64;
            uint32_t dK = sK + nb * 64 * QKSTRIDE * 4;
            uint32_t dV = sV + nb * 64 * 64 * 4;
#pragma unroll
            for (int t = 0; t < 4; t++) {
                int i = tid + t * 256;
                int r = i >> 4, c = (i & 15) << 2;
                cp16(dK + (r * QKSTRIDE + c) * 4, Kt + r * 64 + c);
                cp16(dV + (r * 64 + c) * 4,       Vt + r * 64 + c);
            }
        }
        cp_commit();       // empty group when kt==15 keeps wait_group balanced

        // S = Qs @ Ks^T, reduction packed over channel pairs
        u64 acc[4][4];
#pragma unroll
        for (int i = 0; i < 4; i++)
#pragma unroll
            for (int j = 0; j < 4; j++) acc[i][j] = 0ULL;

#pragma unroll 4
        for (int c = 0; c < 64; c += 4) {
            ulonglong2 q[4], kk[4];
#pragma unroll
            for (int i = 0; i < 4; i++)
                q[i] = *(const ulonglong2*)&Qs[(ty * 4 + i) * QKSTRIDE + c];
#pragma unroll
            for (int j = 0; j < 4; j++)
                kk[j] = *(const ulonglong2*)&Ks[(tx + 16 * j) * QKSTRIDE + c];
#pragma unroll
            for (int i = 0; i < 4; i++)
#pragma unroll
                for (int j = 0; j < 4; j++) {
                    acc[i][j] = ffma2(q[i].x, kk[j].x, acc[i][j]);
                    acc[i][j] = ffma2(q[i].y, kk[j].y, acc[i][j]);
                }
        }

        float s[4][4];
#pragma unroll
        for (int i = 0; i < 4; i++)
#pragma unroll
            for (int j = 0; j < 4; j++) {
                float2 p = u2f2(acc[i][j]);
                s[i][j] = p.x + p.y;
            }

        // online softmax update; P -> smem
#pragma unroll
        for (int i = 0; i < 4; i++) {
            float mx = fmaxf(fmaxf(s[i][0], s[i][1]), fmaxf(s[i][2], s[i][3]));
#pragma unroll
            for (int d = 1; d < 16; d <<= 1)
                mx = fmaxf(mx, __shfl_xor_sync(0xffffffffu, mx, d, 16));
            float mnew = fmaxf(mrun[i], mx);
            float corr = __expf(mrun[i] - mnew);
            float rs = 0.0f;
#pragma unroll
            for (int j = 0; j < 4; j++) {
                float p = __expf(s[i][j] - mnew);
                s[i][j] = p;
                rs += p;
            }
#pragma unroll
            for (int d = 1; d < 16; d <<= 1)
                rs += __shfl_xor_sync(0xffffffffu, rs, d, 16);
            lrun[i] = lrun[i] * corr + rs;
            mrun[i] = mnew;
            u64 c2 = dup2(corr);
            o2[i][0] = fmul2(o2[i][0], c2);
            o2[i][1] = fmul2(o2[i][1], c2);
#pragma unroll
            for (int j = 0; j < 4; j++)
                Ps[(ty * 4 + i) * QKSTRIDE + tx + 16 * j] = s[i][j];
        }
        __syncthreads();

        // O += P @ V   (output cols tx*4 + 0..3 as two packed pairs)
#pragma unroll 4
        for (int k0 = 0; k0 < 64; k0 += 4) {
            u64 va[4][2];
#pragma unroll
            for (int kk = 0; kk < 4; kk++) {
                ulonglong2 t = *(const ulonglong2*)&Vs[(k0 + kk) * 64 + tx * 4];
                va[kk][0] = t.x;
                va[kk][1] = t.y;
            }
#pragma unroll
            for (int i = 0; i < 4; i++) {
                float4 p = *(const float4*)&Ps[(ty * 4 + i) * QKSTRIDE + k0];
                u64 d0 = dup2(p.x), d1 = dup2(p.y), d2 = dup2(p.z), d3 = dup2(p.w);
                o2[i][0] = ffma2(d0, va[0][0], o2[i][0]);
                o2[i][1] = ffma2(d0, va[0][1], o2[i][1]);
                o2[i][0] = ffma2(d1, va[1][0], o2[i][0]);
                o2[i][1] = ffma2(d1, va[1][1], o2[i][1]);
                o2[i][0] = ffma2(d2, va[2][0], o2[i][0]);
                o2[i][1] = ffma2(d2, va[2][1], o2[i][1]);
                o2[i][0] = ffma2(d3, va[3][0], o2[i][0]);
                o2[i][1] = ffma2(d3, va[3][1], o2[i][1]);
            }
        }
    }

    // epilogue: Xout = O / l + Xin
    const float* Xin = g_X[pp] + ((size_t)b * NN + n0) * CC;
    float* Xout = g_X[pp ^ 1] + ((size_t)b * NN + n0) * CC;
#pragma unroll
    for (int i = 0; i < 4; i++) {
        float inv = 1.0f / lrun[i];
        int r = ty * 4 + i;
        float2 a = u2f2(o2[i][0]);
        float2 bb2 = u2f2(o2[i][1]);
        float4 xi = *(const float4*)&Xin[r * 64 + tx * 4];
        float4 res;
        res.x = a.x * inv + xi.x;
        res.y = a.y * inv + xi.y;
        res.z = bb2.x * inv + xi.z;
        res.w = bb2.y * inv + xi.w;
        *(float4*)&Xout[r * 64 + tx * 4] = res;
    }
}

// ---------------------------------------------------------------------------
// Head: pred[b] = mean_c(X[b]) @ last_W^T + last_b
// ---------------------------------------------------------------------------
__global__ void k_head(const float* __restrict__ lw,
                       const float* __restrict__ lb,
                       float* __restrict__ out) {
    __shared__ float meanv[NN];
    __shared__ float red[8];
    int b = blockIdx.x;
    const float* Xb = g_X[0] + (size_t)b * NN * CC;   // DEPTH even -> final in buf 0

    for (int n = threadIdx.x; n < NN; n += 256) {
        const float4* p = (const float4*)(Xb + (size_t)n * CC);
        float s = 0.0f;
#pragma unroll
        for (int q = 0; q < 16; q++) {
            float4 v = p[q];
            s += v.x + v.y + v.z + v.w;
        }
        meanv[n] = s * (1.0f / 64.0f);
    }
    __syncthreads();

    for (int cls = 0; cls < NCLS; cls++) {
        float s = 0.0f;
        for (int n = threadIdx.x; n < NN; n += 256)
            s += meanv[n] * lw[cls * NN + n];
#pragma unroll
        for (int d = 16; d; d >>= 1) s += __shfl_xor_sync(0xffffffffu, s, d);
        if ((threadIdx.x & 31) == 0) red[threadIdx.x >> 5] = s;
        __syncthreads();
        if (threadIdx.x == 0) {
            float t = 0.0f;
#pragma unroll
            for (int w = 0; w < 8; w++) t += red[w];
            out[b * NCLS + cls] = t + lb[cls];
        }
        __syncthreads();
    }
}

// ---------------------------------------------------------------------------
extern "C" void kernel_launch(void* const* d_in, const int* in_sizes, int n_in,
                              void* d_out, int out_size) {
    (void)in_sizes; (void)n_in; (void)out_size;
    const float* img = (const float*)d_in[0];
    const float* WV  = (const float*)d_in[1];
    const float* WK  = (const float*)d_in[2];
    const float* WQ  = (const float*)d_in[3];
    const float* lw  = (const float*)d_in[4];
    const float* lb  = (const float*)d_in[5];
    float* out = (float*)d_out;

    const int QKV_SMEM  = (64 * XSTRIDE + 64 * 192) * 4;                       // ~66.6 KB
    const int ATTN_SMEM = (64 * QKSTRIDE * 2 + 2 * 64 * QKSTRIDE + 2 * 64 * 64) * 4;  // 100 KB
    cudaFuncSetAttribute(k_qkv,  cudaFuncAttributeMaxDynamicSharedMemorySize, QKV_SMEM);
    cudaFuncSetAttribute(k_attn, cudaFuncAttributeMaxDynamicSharedMemorySize, ATTN_SMEM);

    dim3 grid(16, 32), blk(256);
    k_transpose<<<grid, blk>>>(img);
    for (int l = 0; l < DEPTH; l++) {
        k_qkv<<<grid, blk, QKV_SMEM>>>(WQ, WK, WV, l & 1);
        k_attn<<<grid, blk, ATTN_SMEM>>>(l & 1);
    }
    k_head<<<32, blk>>>(lw, lb, out);
}

// round 4
// speedup vs baseline: 1.3512x; 1.0664x over previous
#include <cuda_runtime.h>
#include <cuda_bf16.h>
#include <cstdint>

#define BB 32
#define CC 64
#define NN 1024
#define DEPTH 8
#define NCLS 10

using u64 = unsigned long long;

static __device__ float g_X[2][BB * NN * CC];   // ping-pong token states
static __device__ float g_Q[BB * NN * CC];
static __device__ float g_K[BB * NN * CC];
static __device__ float g_V[BB * NN * CC];

// ---------------- packed fp32 helpers (Blackwell f32x2 pipe) ----------------
__device__ __forceinline__ u64 ffma2(u64 a, u64 b, u64 c) {
    u64 d;
    asm("fma.rn.f32x2 %0, %1, %2, %3;" : "=l"(d) : "l"(a), "l"(b), "l"(c));
    return d;
}
__device__ __forceinline__ u64 fmul2(u64 a, u64 b) {
    u64 d;
    asm("mul.rn.f32x2 %0, %1, %2;" : "=l"(d) : "l"(a), "l"(b));
    return d;
}
__device__ __forceinline__ u64 dup2(float x) {
    u64 r;
    asm("mov.b64 %0, {%1, %1};" : "=l"(r) : "f"(x));
    return r;
}
__device__ __forceinline__ float2 u2f2(u64 v) {
    float2 r;
    asm("mov.b64 {%0, %1}, %2;" : "=f"(r.x), "=f"(r.y) : "l"(v));
    return r;
}

// ---------------- cp.async helpers ----------------
__device__ __forceinline__ void cp16(uint32_t dst, const float* src) {
    asm volatile("cp.async.cg.shared.global [%0], [%1], 16;" :: "r"(dst), "l"(src));
}
__device__ __forceinline__ void cp_commit() {
    asm volatile("cp.async.commit_group;" ::: "memory");
}
__device__ __forceinline__ void cp_wait0() {
    asm volatile("cp.async.wait_group 0;" ::: "memory");
}

// ---------------------------------------------------------------------------
// Transpose: image (B,C,1024) -> X[0] (B,1024,C)
// ---------------------------------------------------------------------------
__global__ void k_transpose(const float* __restrict__ img) {
    __shared__ float t[64][65];
    int b = blockIdx.y;
    int n0 = blockIdx.x * 64;
    const float* src = img + (size_t)b * CC * NN;
    for (int idx = threadIdx.x; idx < 64 * 64; idx += 256) {
        int c = idx >> 6, n = idx & 63;
        t[c][n] = src[c * NN + n0 + n];
    }
    __syncthreads();
    float* dst = g_X[0] + ((size_t)b * NN + n0) * CC;
    for (int idx = threadIdx.x; idx < 64 * 64; idx += 256) {
        int n = idx >> 6, c = idx & 63;
        dst[n * CC + c] = t[c][n];
    }
}

// ---------------------------------------------------------------------------
// Fused QKV (f32x2): Q = (X @ WQ) * scale, K = X @ WK, V = X @ WV
// ---------------------------------------------------------------------------
#define XSTRIDE 68

__global__ void __launch_bounds__(256) k_qkv(const float* __restrict__ WQ,
                                             const float* __restrict__ WK,
                                             const float* __restrict__ WV,
                                             int pp) {
    extern __shared__ float sm[];
    float* Xs = sm;                   // 64 x 68
    float* Ws = sm + 64 * XSTRIDE;    // 64 x 192  (Q|K|V columns)
    uint32_t sXs = (uint32_t)__cvta_generic_to_shared(Xs);
    uint32_t sWs = (uint32_t)__cvta_generic_to_shared(Ws);

    int b = blockIdx.y;
    int n0 = blockIdx.x * 64;
    int tid = threadIdx.x;

    const float* Xin = g_X[pp] + ((size_t)b * NN + n0) * CC;
#pragma unroll
    for (int t = 0; t < 4; t++) {
        int i = tid + t * 256;
        int r = i >> 4, c = (i & 15) << 2;
        cp16(sXs + (r * XSTRIDE + c) * 4, Xin + r * 64 + c);
        cp16(sWs + (r * 192 + c) * 4,       WQ + r * 64 + c);
        cp16(sWs + (r * 192 + 64 + c) * 4,  WK + r * 64 + c);
        cp16(sWs + (r * 192 + 128 + c) * 4, WV + r * 64 + c);
    }
    cp_commit();

    int tx = tid & 15, ty = tid >> 4;
    u64 acc[4][6];
#pragma unroll
    for (int i = 0; i < 4; i++)
#pragma unroll
        for (int j = 0; j < 6; j++) acc[i][j] = 0ULL;

    cp_wait0();
    __syncthreads();

#pragma unroll 2
    for (int k0 = 0; k0 < 64; k0 += 4) {
        float4 xv[4];
#pragma unroll
        for (int i = 0; i < 4; i++)
            xv[i] = *(const float4*)&Xs[(ty * 4 + i) * XSTRIDE + k0];
#pragma unroll
        for (int kk = 0; kk < 4; kk++) {
            u64 wv[6];
#pragma unroll
            for (int j = 0; j < 6; j++)
                wv[j] = *(const u64*)&Ws[(k0 + kk) * 192 + tx * 2 + 32 * j];
            u64 xd[4];
            xd[0] = dup2(kk == 0 ? xv[0].x : kk == 1 ? xv[0].y : kk == 2 ? xv[0].z : xv[0].w);
            xd[1] = dup2(kk == 0 ? xv[1].x : kk == 1 ? xv[1].y : kk == 2 ? xv[1].z : xv[1].w);
            xd[2] = dup2(kk == 0 ? xv[2].x : kk == 1 ? xv[2].y : kk == 2 ? xv[2].z : xv[2].w);
            xd[3] = dup2(kk == 0 ? xv[3].x : kk == 1 ? xv[3].y : kk == 2 ? xv[3].z : xv[3].w);
#pragma unroll
            for (int i = 0; i < 4; i++)
#pragma unroll
                for (int j = 0; j < 6; j++)
                    acc[i][j] = ffma2(xd[i], wv[j], acc[i][j]);
        }
    }

    const u64 scale2 = dup2(0.03125f);   // 1/sqrt(1024)
    size_t base = ((size_t)b * NN + n0) * CC;
    float* Qo = g_Q + base;
    float* Ko = g_K + base;
    float* Vo = g_V + base;
#pragma unroll
    for (int i = 0; i < 4; i++) {
        int r = ty * 4 + i;
        int co = tx * 2;
#pragma unroll
        for (int j = 0; j < 2; j++) {
            *(u64*)&Qo[r * 64 + co + 32 * j] = fmul2(acc[i][j], scale2);
            *(u64*)&Ko[r * 64 + co + 32 * j] = acc[i][2 + j];
            *(u64*)&Vo[r * 64 + co + 32 * j] = acc[i][4 + j];
        }
    }
}

// ---------------------------------------------------------------------------
// Flash attention + residual. 128 q-rows/CTA, 256 threads, 8x4 reg tile.
// K/V cp.async ring-3, Ps double-buffered, 1 barrier per key-tile.
// Pipeline: bar -> cp(kt+1) -> S(kt) -> PV(kt-1) -> softmax(kt) -> corr.
// ---------------------------------------------------------------------------
#define KSTR 68
#define QROWS 128

__device__ __forceinline__ void pv_accum(const float* __restrict__ Vp,
                                         const float* __restrict__ Pr,
                                         u64 (&o2)[8][2], int tx, int ty) {
#pragma unroll 2
    for (int k0 = 0; k0 < 64; k0 += 4) {
        ulonglong2 vv[4];
#pragma unroll
        for (int kk = 0; kk < 4; kk++)
            vv[kk] = *(const ulonglong2*)&Vp[(k0 + kk) * 64 + tx * 4];
#pragma unroll
        for (int i = 0; i < 8; i++) {
            float4 p = *(const float4*)&Pr[(ty * 8 + i) * KSTR + k0];
            u64 d;
            d = dup2(p.x);
            o2[i][0] = ffma2(d, vv[0].x, o2[i][0]);
            o2[i][1] = ffma2(d, vv[0].y, o2[i][1]);
            d = dup2(p.y);
            o2[i][0] = ffma2(d, vv[1].x, o2[i][0]);
            o2[i][1] = ffma2(d, vv[1].y, o2[i][1]);
            d = dup2(p.z);
            o2[i][0] = ffma2(d, vv[2].x, o2[i][0]);
            o2[i][1] = ffma2(d, vv[2].y, o2[i][1]);
            d = dup2(p.w);
            o2[i][0] = ffma2(d, vv[3].x, o2[i][0]);
            o2[i][1] = ffma2(d, vv[3].y, o2[i][1]);
        }
    }
}

__global__ void __launch_bounds__(256) k_attn(int pp) {
    extern __shared__ float sm[];
    float* Qs = sm;                            // 128 x 68
    float* Ks = Qs + QROWS * KSTR;             // 3 x (64 x 68)
    float* Vs = Ks + 3 * 64 * KSTR;            // 3 x (64 x 64)
    float* Ps = Vs + 3 * 64 * 64;              // 2 x (128 x 68)
    uint32_t sQ = (uint32_t)__cvta_generic_to_shared(Qs);
    uint32_t sK = (uint32_t)__cvta_generic_to_shared(Ks);
    uint32_t sV = (uint32_t)__cvta_generic_to_shared(Vs);

    int b = blockIdx.y;
    int n0 = blockIdx.x * QROWS;
    int tid = threadIdx.x, tx = tid & 15, ty = tid >> 4;

    const float* Qg = g_Q + ((size_t)b * NN + n0) * CC;
    const float* Kg = g_K + (size_t)b * NN * CC;
    const float* Vg = g_V + (size_t)b * NN * CC;

    // prologue: Q (8 chunks/thread) + K0/V0 (4+4)
#pragma unroll
    for (int t = 0; t < 8; t++) {
        int i = tid + t * 256;
        int r = i >> 4, c = (i & 15) << 2;
        cp16(sQ + (r * KSTR + c) * 4, Qg + r * 64 + c);
    }
#pragma unroll
    for (int t = 0; t < 4; t++) {
        int i = tid + t * 256;
        int r = i >> 4, c = (i & 15) << 2;
        cp16(sK + (r * KSTR + c) * 4, Kg + r * 64 + c);
        cp16(sV + (r * 64 + c) * 4,   Vg + r * 64 + c);
    }
    cp_commit();

    u64 o2[8][2];
    float mrun[8], lrun[8];
#pragma unroll
    for (int i = 0; i < 8; i++) {
        mrun[i] = -1e30f;
        lrun[i] = 0.0f;
        o2[i][0] = 0ULL;
        o2[i][1] = 0ULL;
    }

#pragma unroll 1
    for (int kt = 0; kt < 16; ++kt) {
        cp_wait0();        // tile kt resident
        __syncthreads();   // cp visible; Ps(kt-1) visible; prev reads done

        // prefetch tile kt+1 into ring slot (kt+1)%3
        if (kt + 1 < 16) {
            int s = (kt + 1) % 3;
            const float* Kt = Kg + (kt + 1) * 64 * 64;
            const float* Vt = Vg + (kt + 1) * 64 * 64;
            uint32_t dK = sK + s * 64 * KSTR * 4;
            uint32_t dV = sV + s * 64 * 64 * 4;
#pragma unroll
            for (int t = 0; t < 4; t++) {
                int i = tid + t * 256;
                int r = i >> 4, c = (i & 15) << 2;
                cp16(dK + (r * KSTR + c) * 4, Kt + r * 64 + c);
                cp16(dV + (r * 64 + c) * 4,   Vt + r * 64 + c);
            }
        }
        cp_commit();

        // ---- S = Qs @ K(kt)^T, packed over channel pairs ----
        const float* Kp = Ks + (kt % 3) * 64 * KSTR;
        u64 acc[8][4];
#pragma unroll
        for (int i = 0; i < 8; i++)
#pragma unroll
            for (int j = 0; j < 4; j++) acc[i][j] = 0ULL;

#pragma unroll 2
        for (int c0 = 0; c0 < 64; c0 += 4) {
            ulonglong2 qv[8], kv[4];
#pragma unroll
            for (int i = 0; i < 8; i++)
                qv[i] = *(const ulonglong2*)&Qs[(ty * 8 + i) * KSTR + c0];
#pragma unroll
            for (int j = 0; j < 4; j++)
                kv[j] = *(const ulonglong2*)&Kp[(tx + 16 * j) * KSTR + c0];
#pragma unroll
            for (int i = 0; i < 8; i++)
#pragma unroll
                for (int j = 0; j < 4; j++) {
                    acc[i][j] = ffma2(qv[i].x, kv[j].x, acc[i][j]);
                    acc[i][j] = ffma2(qv[i].y, kv[j].y, acc[i][j]);
                }
        }

        float s[8][4];
#pragma unroll
        for (int i = 0; i < 8; i++)
#pragma unroll
            for (int j = 0; j < 4; j++) {
                float2 p = u2f2(acc[i][j]);
                s[i][j] = p.x + p.y;
            }

        // ---- PV(kt-1): overlaps softmax latency below via scheduler ----
        if (kt > 0)
            pv_accum(Vs + ((kt - 1) % 3) * 4096,
                     Ps + ((kt - 1) & 1) * QROWS * KSTR, o2, tx, ty);

        // ---- online softmax for tile kt; write Ps[kt&1]; defer corr ----
        float corr[8];
        float* Pw = Ps + (kt & 1) * QROWS * KSTR;
#pragma unroll
        for (int i = 0; i < 8; i++) {
            float mx = fmaxf(fmaxf(s[i][0], s[i][1]), fmaxf(s[i][2], s[i][3]));
#pragma unroll
            for (int d = 1; d < 16; d <<= 1)
                mx = fmaxf(mx, __shfl_xor_sync(0xffffffffu, mx, d, 16));
            float mnew = fmaxf(mrun[i], mx);
            corr[i] = __expf(mrun[i] - mnew);
            float rs = 0.0f;
#pragma unroll
            for (int j = 0; j < 4; j++) {
                float p = __expf(s[i][j] - mnew);
                s[i][j] = p;
                rs += p;
            }
#pragma unroll
            for (int d = 1; d < 16; d <<= 1)
                rs += __shfl_xor_sync(0xffffffffu, rs, d, 16);
            lrun[i] = lrun[i] * corr[i] + rs;
            mrun[i] = mnew;
#pragma unroll
            for (int j = 0; j < 4; j++)
                Pw[(ty * 8 + i) * KSTR + tx + 16 * j] = s[i][j];
        }

        // ---- apply correction AFTER PV(kt-1) contributions ----
#pragma unroll
        for (int i = 0; i < 8; i++) {
            u64 c2 = dup2(corr[i]);
            o2[i][0] = fmul2(o2[i][0], c2);
            o2[i][1] = fmul2(o2[i][1], c2);
        }
    }

    // tail: PV for last tile (kt=15), after making Ps[1] visible
    __syncthreads();
    pv_accum(Vs + (15 % 3) * 4096, Ps + (15 & 1) * QROWS * KSTR, o2, tx, ty);

    // epilogue: Xout = O / l + Xin
    const float* Xin = g_X[pp] + ((size_t)b * NN + n0) * CC;
    float* Xout = g_X[pp ^ 1] + ((size_t)b * NN + n0) * CC;
#pragma unroll
    for (int i = 0; i < 8; i++) {
        float inv = 1.0f / lrun[i];
        int r = ty * 8 + i;
        float2 a = u2f2(o2[i][0]);
        float2 bb2 = u2f2(o2[i][1]);
        float4 xi = *(const float4*)&Xin[r * 64 + tx * 4];
        float4 res;
        res.x = a.x * inv + xi.x;
        res.y = a.y * inv + xi.y;
        res.z = bb2.x * inv + xi.z;
        res.w = bb2.y * inv + xi.w;
        *(float4*)&Xout[r * 64 + tx * 4] = res;
    }
}

// ---------------------------------------------------------------------------
// Head: pred[b] = mean_c(X[b]) @ last_W^T + last_b
// ---------------------------------------------------------------------------
__global__ void k_head(const float* __restrict__ lw,
                       const float* __restrict__ lb,
                       float* __restrict__ out) {
    __shared__ float meanv[NN];
    __shared__ float red[8];
    int b = blockIdx.x;
    const float* Xb = g_X[0] + (size_t)b * NN * CC;   // DEPTH even -> final in buf 0

    for (int n = threadIdx.x; n < NN; n += 256) {
        const float4* p = (const float4*)(Xb + (size_t)n * CC);
        float s = 0.0f;
#pragma unroll
        for (int q = 0; q < 16; q++) {
            float4 v = p[q];
            s += v.x + v.y + v.z + v.w;
        }
        meanv[n] = s * (1.0f / 64.0f);
    }
    __syncthreads();

    for (int cls = 0; cls < NCLS; cls++) {
        float s = 0.0f;
        for (int n = threadIdx.x; n < NN; n += 256)
            s += meanv[n] * lw[cls * NN + n];
#pragma unroll
        for (int d = 16; d; d >>= 1) s += __shfl_xor_sync(0xffffffffu, s, d);
        if ((threadIdx.x & 31) == 0) red[threadIdx.x >> 5] = s;
        __syncthreads();
        if (threadIdx.x == 0) {
            float t = 0.0f;
#pragma unroll
            for (int w = 0; w < 8; w++) t += red[w];
            out[b * NCLS + cls] = t + lb[cls];
        }
        __syncthreads();
    }
}

// ---------------------------------------------------------------------------
extern "C" void kernel_launch(void* const* d_in, const int* in_sizes, int n_in,
                              void* d_out, int out_size) {
    (void)in_sizes; (void)n_in; (void)out_size;
    const float* img = (const float*)d_in[0];
    const float* WV  = (const float*)d_in[1];
    const float* WK  = (const float*)d_in[2];
    const float* WQ  = (const float*)d_in[3];
    const float* lw  = (const float*)d_in[4];
    const float* lb  = (const float*)d_in[5];
    float* out = (float*)d_out;

    const int QKV_SMEM  = (64 * XSTRIDE + 64 * 192) * 4;
    const int ATTN_SMEM = (QROWS * KSTR + 3 * 64 * KSTR + 3 * 64 * 64 + 2 * QROWS * KSTR) * 4; // 205824
    cudaFuncSetAttribute(k_qkv,  cudaFuncAttributeMaxDynamicSharedMemorySize, QKV_SMEM);
    cudaFuncSetAttribute(k_attn, cudaFuncAttributeMaxDynamicSharedMemorySize, ATTN_SMEM);

    dim3 gq(16, 32), ga(8, 32), blk(256);
    k_transpose<<<gq, blk>>>(img);
    for (int l = 0; l < DEPTH; l++) {
        k_qkv<<<gq, blk, QKV_SMEM>>>(WQ, WK, WV, l & 1);
        k_attn<<<ga, blk, ATTN_SMEM>>>(l & 1);
    }
    k_head<<<32, blk>>>(lw, lb, out);
}